// round 8
// baseline (speedup 1.0000x reference)
#include <cuda_runtime.h>
#include <cstdint>
#include <math.h>

#define TOKENS 32768
#define DMODEL 1024
#define NEXP   64
#define CAP    1024
#define GEMM_BLOCKS 512   /* 32768 / 64 */

// ---------------- scratch (device globals, no allocation) ----------------
__device__ float g_pmax[GEMM_BLOCKS * NEXP];
__device__ float g_gmax[NEXP];
__device__ float g_sum[NEXP];
__device__ float g_lT[(size_t)NEXP * TOKENS];   // logits transposed [e][t], 8.4 MB

// packed 2-lane fp32 FMA: per-lane IEEE RN, bitwise == __fmaf_rn per lane
__device__ __forceinline__ void ffma2(unsigned long long& d,
                                      unsigned long long a,
                                      unsigned long long b) {
    asm("fma.rn.f32x2 %0, %1, %2, %0;" : "+l"(d) : "l"(a), "l"(b));
}
__device__ __forceinline__ float lo32(unsigned long long v) {
    return __uint_as_float((unsigned)v);
}
__device__ __forceinline__ float hi32(unsigned long long v) {
    return __uint_as_float((unsigned)(v >> 32));
}

// ---------------- GEMM: logits = x @ W + b, 2-way block-split-K ----------
// Bitwise contract (matches reference): per output,
//   acc_lo = ascending-k FMA chain over k in [0,512)
//   acc_hi = ascending-k FMA chain over k in [512,1024)
//   logit  = fl(fl(acc_lo + acc_hi) + bias)
// FFMA2 packs two adjacent n-outputs per instruction; each lane is still an
// independent scalar RN-FMA chain in the same order.
#define GEMM_SMEM (64*65*8 + 64*64*4 + 16*64*4)   /* As2 + Bs + red = 53760 */

__global__ __launch_bounds__(256) void gemm_split2_kernel(
    const float* __restrict__ x, const float* __restrict__ W,
    const float* __restrict__ bias_in, float* __restrict__ logits)
{
    extern __shared__ unsigned char dynsm[];
    float2* As2 = (float2*)dynsm;                                // [64][65] duplicated
    float*  Bs  = (float*)(dynsm + 64 * 65 * sizeof(float2));    // [64][64]
    float*  red = Bs + 64 * 64;                                  // [16][64]

    const int tid = threadIdx.x;
    const int tx = tid & 15;       // n0 = tx*4
    const int ty = tid >> 4;       // m0 = ty*4
    const int m_base = blockIdx.x * 64;
    const float* xblk = x + (size_t)m_base * DMODEL;

    unsigned long long acc2[4][2], accL2[4][2];
#pragma unroll
    for (int i = 0; i < 4; i++) { acc2[i][0] = 0ull; acc2[i][1] = 0ull; }

#pragma unroll 1
    for (int half = 0; half < 2; half++) {
#pragma unroll 1
        for (int kt = 0; kt < 8; kt++) {
            const int kc = half * 512 + kt * 64;
            // x tile -> As2 duplicated (a,a)
#pragma unroll
            for (int j = 0; j < 4; j++) {
                int lin = tid + j * 256;          // float4 index
                int m = lin >> 4, k4 = lin & 15;
                float4 v = *(const float4*)(xblk + (size_t)m * DMODEL + kc + k4 * 4);
                As2[m * 65 + k4 * 4 + 0] = make_float2(v.x, v.x);
                As2[m * 65 + k4 * 4 + 1] = make_float2(v.y, v.y);
                As2[m * 65 + k4 * 4 + 2] = make_float2(v.z, v.z);
                As2[m * 65 + k4 * 4 + 3] = make_float2(v.w, v.w);
            }
            // W tile -> Bs
#pragma unroll
            for (int j = 0; j < 4; j++) {
                int lin = tid + j * 256;
                int kk = lin >> 4, n4 = lin & 15;
                *(float4*)&Bs[kk * 64 + n4 * 4] =
                    *(const float4*)(W + (size_t)(kc + kk) * NEXP + n4 * 4);
            }
            __syncthreads();

            const unsigned long long* a0p = (const unsigned long long*)(As2 + (ty * 4 + 0) * 65);
            const unsigned long long* a1p = (const unsigned long long*)(As2 + (ty * 4 + 1) * 65);
            const unsigned long long* a2p = (const unsigned long long*)(As2 + (ty * 4 + 2) * 65);
            const unsigned long long* a3p = (const unsigned long long*)(As2 + (ty * 4 + 3) * 65);

#pragma unroll 16
            for (int kk = 0; kk < 64; kk++) {
                unsigned long long a0 = a0p[kk];
                unsigned long long a1 = a1p[kk];
                unsigned long long a2 = a2p[kk];
                unsigned long long a3 = a3p[kk];
                const unsigned long long* bp =
                    (const unsigned long long*)(Bs + kk * 64 + tx * 4);
                unsigned long long b0 = bp[0], b1 = bp[1];
                ffma2(acc2[0][0], a0, b0); ffma2(acc2[0][1], a0, b1);
                ffma2(acc2[1][0], a1, b0); ffma2(acc2[1][1], a1, b1);
                ffma2(acc2[2][0], a2, b0); ffma2(acc2[2][1], a2, b1);
                ffma2(acc2[3][0], a3, b0); ffma2(acc2[3][1], a3, b1);
            }
            __syncthreads();
        }
        if (half == 0) {
#pragma unroll
            for (int i = 0; i < 4; i++) {
                accL2[i][0] = acc2[i][0]; accL2[i][1] = acc2[i][1];
                acc2[i][0] = 0ull;        acc2[i][1] = 0ull;
            }
        }
    }

    // epilogue: unpack, combine halves, +bias (exact R7 order)
    float4 bb = *(const float4*)(bias_in + tx * 4);
    float bias[4] = {bb.x, bb.y, bb.z, bb.w};
    float fin[4][4];
#pragma unroll
    for (int i = 0; i < 4; i++) {
        float lo0 = lo32(accL2[i][0]), lo1 = hi32(accL2[i][0]);
        float lo2 = lo32(accL2[i][1]), lo3 = hi32(accL2[i][1]);
        float hi0 = lo32(acc2[i][0]),  hi1 = hi32(acc2[i][0]);
        float hi2 = lo32(acc2[i][1]),  hi3 = hi32(acc2[i][1]);
        fin[i][0] = __fadd_rn(__fadd_rn(lo0, hi0), bias[0]);
        fin[i][1] = __fadd_rn(__fadd_rn(lo1, hi1), bias[1]);
        fin[i][2] = __fadd_rn(__fadd_rn(lo2, hi2), bias[2]);
        fin[i][3] = __fadd_rn(__fadd_rn(lo3, hi3), bias[3]);
    }

    float cmax[4] = {-3.4e38f, -3.4e38f, -3.4e38f, -3.4e38f};
#pragma unroll
    for (int i = 0; i < 4; i++) {
        float4 o = make_float4(fin[i][0], fin[i][1], fin[i][2], fin[i][3]);
        *(float4*)(logits + (size_t)(m_base + ty * 4 + i) * NEXP + tx * 4) = o;
        cmax[0] = fmaxf(cmax[0], o.x); cmax[1] = fmaxf(cmax[1], o.y);
        cmax[2] = fmaxf(cmax[2], o.z); cmax[3] = fmaxf(cmax[3], o.w);
    }
    // transposed store: logitsT[n][m], float4 along m
#pragma unroll
    for (int j = 0; j < 4; j++) {
        float4 t = make_float4(fin[0][j], fin[1][j], fin[2][j], fin[3][j]);
        *(float4*)(g_lT + (size_t)(tx * 4 + j) * TOKENS + m_base + ty * 4) = t;
    }
#pragma unroll
    for (int j = 0; j < 4; j++) red[ty * 64 + tx * 4 + j] = cmax[j];
    __syncthreads();
    if (tid < 64) {
        float m = red[tid];
#pragma unroll
        for (int w = 1; w < 16; w++) m = fmaxf(m, red[w * 64 + tid]);
        g_pmax[(size_t)blockIdx.x * NEXP + tid] = m;
    }
}

// ---------------- global column max (order-free, exact) -------------------
__global__ __launch_bounds__(256) void reduce_max_kernel()
{
    __shared__ float sm[256];
    const int e = blockIdx.x;
    float m = -3.4e38f;
    for (int i = threadIdx.x; i < GEMM_BLOCKS; i += 256)
        m = fmaxf(m, g_pmax[(size_t)i * NEXP + e]);
    sm[threadIdx.x] = m; __syncthreads();
    for (int s = 128; s > 0; s >>= 1) {
        if (threadIdx.x < s) sm[threadIdx.x] = fmaxf(sm[threadIdx.x], sm[threadIdx.x + s]);
        __syncthreads();
    }
    if (threadIdx.x == 0) g_gmax[e] = sm[0];
}

// ---------------- S_e = fl32( f64-accurate sum of expf(l - M) ) -----------
__global__ __launch_bounds__(1024) void sum_exp_kernel()
{
    __shared__ double sm[1024];
    const int e = blockIdx.x;
    const float M = g_gmax[e];
    const float4* col = (const float4*)(g_lT + (size_t)e * TOKENS);
    double s = 0.0;
    for (int i = threadIdx.x; i < TOKENS / 4; i += 1024) {
        float4 v = col[i];
        s += (double)expf(__fsub_rn(v.x, M));
        s += (double)expf(__fsub_rn(v.y, M));
        s += (double)expf(__fsub_rn(v.z, M));
        s += (double)expf(__fsub_rn(v.w, M));
    }
    sm[threadIdx.x] = s; __syncthreads();
    for (int st = 512; st > 0; st >>= 1) {
        if (threadIdx.x < st) sm[threadIdx.x] += sm[threadIdx.x + st];
        __syncthreads();
    }
    if (threadIdx.x == 0) g_sum[e] = (float)sm[0];
}

// ---------------- probs = fl( expf(l - M) / S ), vectorized x4 ------------
__global__ __launch_bounds__(256) void probs_kernel(
    const float* __restrict__ logits, float* __restrict__ probs)
{
    __shared__ float sM[64], sS[64];
    if (threadIdx.x < 64) {
        sM[threadIdx.x] = g_gmax[threadIdx.x];
        sS[threadIdx.x] = g_sum[threadIdx.x];
    }
    __syncthreads();
    int i4 = (blockIdx.x * 256 + threadIdx.x) * 4;   // grid covers 2M exactly
    float4 l = *(const float4*)(logits + i4);
    int e0 = i4 & 63;
    float4 p;
    p.x = __fdiv_rn(expf(__fsub_rn(l.x, sM[e0 + 0])), sS[e0 + 0]);
    p.y = __fdiv_rn(expf(__fsub_rn(l.y, sM[e0 + 1])), sS[e0 + 1]);
    p.z = __fdiv_rn(expf(__fsub_rn(l.z, sM[e0 + 2])), sS[e0 + 2]);
    p.w = __fdiv_rn(expf(__fsub_rn(l.w, sM[e0 + 3])), sS[e0 + 3]);
    *(float4*)(probs + i4) = p;
}

// ---------------- exact stable top-1024 on fp32 prob keys -----------------
__device__ __forceinline__ unsigned mono_fwd(float f) {
    unsigned u = __float_as_uint(f);
    return (u & 0x80000000u) ? ~u : (u | 0x80000000u);
}
__device__ __forceinline__ float mono_inv(unsigned m) {
    unsigned u = (m & 0x80000000u) ? (m ^ 0x80000000u) : ~m;
    return __uint_as_float(u);
}

#define TOPK_SMEM (131072 + 8192 + 1024 + 128)

__global__ __launch_bounds__(1024) void topk_kernel(
    float* __restrict__ out_val, float* __restrict__ out_idx)
{
    extern __shared__ unsigned char sm_raw[];
    unsigned*           vals = (unsigned*)sm_raw;                         // 32768
    unsigned long long* cand = (unsigned long long*)(sm_raw + 131072);    // 1024
    unsigned*           hist = (unsigned*)(sm_raw + 131072 + 8192);       // 256
    unsigned*           wsum = (unsigned*)(sm_raw + 131072 + 8192 + 1024);// 32

    __shared__ int      s_sel;
    __shared__ int      s_k;
    __shared__ unsigned s_cnt;
    __shared__ unsigned s_run;

    const int tid = threadIdx.x;
    const int e   = blockIdx.x;
    const int lane = tid & 31, wid = tid >> 5;

    // build prob bit-keys from transposed logits (bitwise == probs_kernel)
    const float M = g_gmax[e];
    const float S = g_sum[e];
    const float4* col = (const float4*)(g_lT + (size_t)e * TOKENS);
    for (int i = tid; i < TOKENS / 4; i += 1024) {
        float4 l = col[i];
        vals[4 * i + 0] = mono_fwd(__fdiv_rn(expf(__fsub_rn(l.x, M)), S));
        vals[4 * i + 1] = mono_fwd(__fdiv_rn(expf(__fsub_rn(l.y, M)), S));
        vals[4 * i + 2] = mono_fwd(__fdiv_rn(expf(__fsub_rn(l.z, M)), S));
        vals[4 * i + 3] = mono_fwd(__fdiv_rn(expf(__fsub_rn(l.w, M)), S));
    }
    if (tid == 0) s_k = CAP;
    __syncthreads();

    // 4-pass MSB radix select -> exact fp32 threshold
    unsigned prefix = 0, pmask = 0;
#pragma unroll
    for (int pass = 0; pass < 4; pass++) {
        const int shift = 24 - 8 * pass;
        if (tid < 256) hist[tid] = 0;
        __syncthreads();
        for (int i = tid; i < TOKENS; i += 1024) {
            unsigned v = vals[i];
            if ((v & pmask) == prefix) atomicAdd(&hist[(v >> shift) & 255u], 1u);
        }
        __syncthreads();
        if (tid == 0) {
            int k = s_k; unsigned cum = 0; int bsel = 0;
            for (int bb = 255; bb >= 0; bb--) {
                unsigned c = hist[bb];
                if (cum + c >= (unsigned)k) { bsel = bb; break; }
                cum += c;
            }
            s_sel = bsel;
            s_k   = k - (int)cum;
        }
        __syncthreads();
        prefix |= ((unsigned)s_sel) << shift;
        pmask  |= 0xFFu << shift;
        __syncthreads();
    }
    const int r = s_k;                 // #elements == threshold still needed
    const unsigned th = prefix;

    // strictly-greater set (exactly 1024 - r, unordered)
    if (tid == 0) { s_cnt = 0; s_run = 0; }
    __syncthreads();
    for (int i = tid; i < TOKENS; i += 1024) {
        unsigned v = vals[i];
        if (v > th) {
            unsigned p = atomicAdd(&s_cnt, 1u);
            cand[p] = ((unsigned long long)v << 32) | (unsigned)(~(unsigned)i);
        }
    }
    __syncthreads();
    const unsigned eqbase = (unsigned)(CAP - r);

    // equals in ascending-index order (stable tie-break = lax.top_k)
    for (int c = 0; c < TOKENS / 1024; c++) {
        int i = c * 1024 + tid;
        int flag = (vals[i] == th) ? 1 : 0;
        unsigned bal = __ballot_sync(0xffffffffu, flag);
        if (lane == 0) wsum[wid] = __popc(bal);
        __syncthreads();
        if (tid == 0) {
            unsigned a = s_run;
            for (int w = 0; w < 32; w++) { unsigned t = wsum[w]; wsum[w] = a; a += t; }
            s_run = a;
        }
        __syncthreads();
        if (flag) {
            unsigned rank = wsum[wid] + __popc(bal & ((1u << lane) - 1u));
            if (rank < (unsigned)r)
                cand[eqbase + rank] =
                    ((unsigned long long)th << 32) | (unsigned)(~(unsigned)i);
        }
        __syncthreads();
    }

    // bitonic sort 1024 keys DESCENDING (value desc, index asc via ~idx)
    for (unsigned kk = 2; kk <= 1024; kk <<= 1) {
        for (unsigned j = kk >> 1; j > 0; j >>= 1) {
            __syncthreads();
            unsigned i = (unsigned)tid, ixj = i ^ j;
            if (ixj > i) {
                unsigned long long a = cand[i], cc = cand[ixj];
                bool swp = ((i & kk) == 0) ? (a < cc) : (a > cc);
                if (swp) { cand[i] = cc; cand[ixj] = a; }
            }
        }
    }
    __syncthreads();

    unsigned long long key = cand[tid];
    unsigned m   = (unsigned)(key >> 32);
    unsigned idx = ~(unsigned)(key & 0xffffffffu);
    out_val[(size_t)e * CAP + tid] = mono_inv(m);
    out_idx[(size_t)e * CAP + tid] = (float)idx;
}

// ---------------- launch ----------------
extern "C" void kernel_launch(void* const* d_in, const int* in_sizes, int n_in,
                              void* d_out, int out_size)
{
    const float* x = (const float*)d_in[0];
    const float* W = (const float*)d_in[1];
    const float* b = (const float*)d_in[2];
    (void)in_sizes; (void)n_in; (void)out_size;

    float* out    = (float*)d_out;
    float* logits = out;                                  // 32768*64
    float* probs  = out + (size_t)TOKENS * NEXP;          // 32768*64
    float* ep     = out + 2 * (size_t)TOKENS * NEXP;      // 64*1024
    float* ei     = ep  + (size_t)NEXP * CAP;             // 64*1024

    cudaFuncSetAttribute(gemm_split2_kernel,
                         cudaFuncAttributeMaxDynamicSharedMemorySize, GEMM_SMEM);
    cudaFuncSetAttribute(topk_kernel,
                         cudaFuncAttributeMaxDynamicSharedMemorySize, TOPK_SMEM);

    gemm_split2_kernel<<<GEMM_BLOCKS, 256, GEMM_SMEM>>>(x, W, b, logits);
    reduce_max_kernel<<<NEXP, 256>>>();
    sum_exp_kernel<<<NEXP, 1024>>>();
    probs_kernel<<<(TOKENS * NEXP) / 1024, 256>>>(logits, probs);
    topk_kernel<<<NEXP, 1024, TOPK_SMEM>>>(ep, ei);
}

// round 9
// speedup vs baseline: 1.1725x; 1.1725x over previous
#include <cuda_runtime.h>
#include <cstdint>
#include <math.h>

#define TOKENS 32768
#define DMODEL 1024
#define NEXP   64
#define CAP    1024
#define GEMM_BLOCKS 512   /* 32768 / 64 */

// ---------------- scratch (device globals, no allocation) ----------------
__device__ float g_pmax[GEMM_BLOCKS * NEXP];
__device__ float g_gmax[NEXP];
__device__ float g_sum[NEXP];
__device__ float g_lT[(size_t)NEXP * TOKENS];   // logits transposed [e][t], 8.4 MB

// ---------------- GEMM: logits = x @ W + b, 2-way block-split-K ----------
// Bitwise contract (== reference): per output,
//   acc_lo = ascending-k FMA chain over k in [0,512)
//   acc_hi = ascending-k FMA chain over k in [512,1024)
//   logit  = fl(fl(acc_lo + acc_hi) + bias)
// (R7-verified scalar kernel; only addition is the transposed g_lT store.)
__global__ __launch_bounds__(256) void gemm_split2_kernel(
    const float* __restrict__ x, const float* __restrict__ W,
    const float* __restrict__ bias_in, float* __restrict__ logits)
{
    __shared__ float As[64][65];   // [m][k] padded
    __shared__ float Bs[64][64];   // [k][n]
    __shared__ float red[16][64];

    const int tid = threadIdx.x;
    const int tx = tid & 15;       // n0 = tx*4
    const int ty = tid >> 4;       // m0 = ty*4
    const int m_base = blockIdx.x * 64;
    const float* xblk = x + (size_t)m_base * DMODEL;

    float acc[4][4];               // current half accumulator
    float accL[4][4];              // saved low-half result
#pragma unroll
    for (int i = 0; i < 4; i++)
#pragma unroll
        for (int j = 0; j < 4; j++) acc[i][j] = 0.0f;

#pragma unroll 1
    for (int half = 0; half < 2; half++) {
        const int kbase = half * 512;
#pragma unroll 1
        for (int kt = 0; kt < 8; kt++) {
            const int kc = kbase + kt * 64;
#pragma unroll
            for (int j = 0; j < 4; j++) {
                int lin = tid + j * 256;           // float4 index
                int m = lin >> 4, k4 = lin & 15;
                float4 v = *(const float4*)(xblk + (size_t)m * DMODEL + kc + k4 * 4);
                As[m][k4 * 4 + 0] = v.x; As[m][k4 * 4 + 1] = v.y;
                As[m][k4 * 4 + 2] = v.z; As[m][k4 * 4 + 3] = v.w;
            }
#pragma unroll
            for (int j = 0; j < 4; j++) {
                int lin = tid + j * 256;
                int kk = lin >> 4, n4 = lin & 15;
                *(float4*)&Bs[kk][n4 * 4] =
                    *(const float4*)(W + (size_t)(kc + kk) * NEXP + n4 * 4);
            }
            __syncthreads();

#pragma unroll 16
            for (int kk = 0; kk < 64; kk++) {
                float a0 = As[ty * 4 + 0][kk];
                float a1 = As[ty * 4 + 1][kk];
                float a2 = As[ty * 4 + 2][kk];
                float a3 = As[ty * 4 + 3][kk];
                float4 bv = *(float4*)&Bs[kk][tx * 4];
                acc[0][0] = __fmaf_rn(a0, bv.x, acc[0][0]);
                acc[0][1] = __fmaf_rn(a0, bv.y, acc[0][1]);
                acc[0][2] = __fmaf_rn(a0, bv.z, acc[0][2]);
                acc[0][3] = __fmaf_rn(a0, bv.w, acc[0][3]);
                acc[1][0] = __fmaf_rn(a1, bv.x, acc[1][0]);
                acc[1][1] = __fmaf_rn(a1, bv.y, acc[1][1]);
                acc[1][2] = __fmaf_rn(a1, bv.z, acc[1][2]);
                acc[1][3] = __fmaf_rn(a1, bv.w, acc[1][3]);
                acc[2][0] = __fmaf_rn(a2, bv.x, acc[2][0]);
                acc[2][1] = __fmaf_rn(a2, bv.y, acc[2][1]);
                acc[2][2] = __fmaf_rn(a2, bv.z, acc[2][2]);
                acc[2][3] = __fmaf_rn(a2, bv.w, acc[2][3]);
                acc[3][0] = __fmaf_rn(a3, bv.x, acc[3][0]);
                acc[3][1] = __fmaf_rn(a3, bv.y, acc[3][1]);
                acc[3][2] = __fmaf_rn(a3, bv.z, acc[3][2]);
                acc[3][3] = __fmaf_rn(a3, bv.w, acc[3][3]);
            }
            __syncthreads();
        }
        if (half == 0) {
#pragma unroll
            for (int i = 0; i < 4; i++)
#pragma unroll
                for (int j = 0; j < 4; j++) { accL[i][j] = acc[i][j]; acc[i][j] = 0.0f; }
        }
    }

    float4 bb = *(const float4*)(bias_in + tx * 4);
    float bias[4] = {bb.x, bb.y, bb.z, bb.w};
    float fin[4][4];
#pragma unroll
    for (int i = 0; i < 4; i++) {
        fin[i][0] = __fadd_rn(__fadd_rn(accL[i][0], acc[i][0]), bias[0]);
        fin[i][1] = __fadd_rn(__fadd_rn(accL[i][1], acc[i][1]), bias[1]);
        fin[i][2] = __fadd_rn(__fadd_rn(accL[i][2], acc[i][2]), bias[2]);
        fin[i][3] = __fadd_rn(__fadd_rn(accL[i][3], acc[i][3]), bias[3]);
    }

    float cmax[4] = {-3.4e38f, -3.4e38f, -3.4e38f, -3.4e38f};
#pragma unroll
    for (int i = 0; i < 4; i++) {
        float4 o = make_float4(fin[i][0], fin[i][1], fin[i][2], fin[i][3]);
        *(float4*)(logits + (size_t)(m_base + ty * 4 + i) * NEXP + tx * 4) = o;
        cmax[0] = fmaxf(cmax[0], o.x); cmax[1] = fmaxf(cmax[1], o.y);
        cmax[2] = fmaxf(cmax[2], o.z); cmax[3] = fmaxf(cmax[3], o.w);
    }
    // transposed store: g_lT[n][m], float4 along m
#pragma unroll
    for (int j = 0; j < 4; j++) {
        float4 t = make_float4(fin[0][j], fin[1][j], fin[2][j], fin[3][j]);
        *(float4*)(g_lT + (size_t)(tx * 4 + j) * TOKENS + m_base + ty * 4) = t;
    }
#pragma unroll
    for (int j = 0; j < 4; j++) red[ty][tx * 4 + j] = cmax[j];
    __syncthreads();
    if (tid < 64) {
        float m = red[0][tid];
#pragma unroll
        for (int w = 1; w < 16; w++) m = fmaxf(m, red[w][tid]);
        g_pmax[(size_t)blockIdx.x * NEXP + tid] = m;
    }
}

// ---------------- global column max (order-free, exact) -------------------
__global__ __launch_bounds__(256) void reduce_max_kernel()
{
    __shared__ float sm[256];
    const int e = blockIdx.x;
    float m = -3.4e38f;
    for (int i = threadIdx.x; i < GEMM_BLOCKS; i += 256)
        m = fmaxf(m, g_pmax[(size_t)i * NEXP + e]);
    sm[threadIdx.x] = m; __syncthreads();
    for (int s = 128; s > 0; s >>= 1) {
        if (threadIdx.x < s) sm[threadIdx.x] = fmaxf(sm[threadIdx.x], sm[threadIdx.x + s]);
        __syncthreads();
    }
    if (threadIdx.x == 0) g_gmax[e] = sm[0];
}

// ---------------- fused: S + exact stable top-1024 per expert -------------
// Computes u = expf(l - M) once; S = fl32(f64 strided+tree sum) in the SAME
// order as the R7/R8 sum_exp kernel (bitwise identical); keys = fdiv(u, S).
__device__ __forceinline__ unsigned mono_fwd(float f) {
    unsigned u = __float_as_uint(f);
    return (u & 0x80000000u) ? ~u : (u | 0x80000000u);
}
__device__ __forceinline__ float mono_inv(unsigned m) {
    unsigned u = (m & 0x80000000u) ? (m ^ 0x80000000u) : ~m;
    return __uint_as_float(u);
}

#define TOPK_SMEM (131072 + 8192 + 8192 + 1024 + 128)

__global__ __launch_bounds__(1024) void topk_kernel(
    float* __restrict__ out_val, float* __restrict__ out_idx)
{
    extern __shared__ unsigned char sm_raw[];
    float*              uval = (float*)sm_raw;                            // 32768 (aliased)
    unsigned*           vals = (unsigned*)sm_raw;                         // aliases uval
    unsigned long long* cand = (unsigned long long*)(sm_raw + 131072);    // 1024
    double*             dred = (double*)(sm_raw + 131072 + 8192);         // 1024
    unsigned*           hist = (unsigned*)(sm_raw + 131072 + 16384);      // 256
    unsigned*           wsum = (unsigned*)(sm_raw + 131072 + 16384 + 1024);// 32

    __shared__ int      s_sel;
    __shared__ int      s_k;
    __shared__ unsigned s_cnt;
    __shared__ unsigned s_run;
    __shared__ float    s_S;

    const int tid = threadIdx.x;
    const int e   = blockIdx.x;
    const int lane = tid & 31, wid = tid >> 5;

    const float M = g_gmax[e];
    const float4* col = (const float4*)(g_lT + (size_t)e * TOKENS);

    // u = expf(l - M), accumulate f64 partial in the sum_exp order
    double s = 0.0;
    for (int i = tid; i < TOKENS / 4; i += 1024) {
        float4 l = col[i];
        float u0 = expf(__fsub_rn(l.x, M));
        float u1 = expf(__fsub_rn(l.y, M));
        float u2 = expf(__fsub_rn(l.z, M));
        float u3 = expf(__fsub_rn(l.w, M));
        uval[4 * i + 0] = u0; uval[4 * i + 1] = u1;
        uval[4 * i + 2] = u2; uval[4 * i + 3] = u3;
        s += (double)u0; s += (double)u1; s += (double)u2; s += (double)u3;
    }
    dred[tid] = s;
    if (tid == 0) s_k = CAP;
    __syncthreads();
    for (int st = 512; st > 0; st >>= 1) {
        if (tid < st) dred[tid] += dred[tid + st];
        __syncthreads();
    }
    if (tid == 0) { s_S = (float)dred[0]; g_sum[e] = s_S; }
    __syncthreads();
    const float S = s_S;

    // convert u -> monotone key of prob = fdiv(u, S), in place
    for (int i = tid; i < TOKENS; i += 1024) {
        float u = uval[i];
        __syncwarp();
        vals[i] = mono_fwd(__fdiv_rn(u, S));
    }
    __syncthreads();

    // 4-pass MSB radix select -> exact fp32 threshold
    unsigned prefix = 0, pmask = 0;
#pragma unroll
    for (int pass = 0; pass < 4; pass++) {
        const int shift = 24 - 8 * pass;
        if (tid < 256) hist[tid] = 0;
        __syncthreads();
        for (int i = tid; i < TOKENS; i += 1024) {
            unsigned v = vals[i];
            if ((v & pmask) == prefix) atomicAdd(&hist[(v >> shift) & 255u], 1u);
        }
        __syncthreads();
        if (tid == 0) {
            int k = s_k; unsigned cum = 0; int bsel = 0;
            for (int bb = 255; bb >= 0; bb--) {
                unsigned c = hist[bb];
                if (cum + c >= (unsigned)k) { bsel = bb; break; }
                cum += c;
            }
            s_sel = bsel;
            s_k   = k - (int)cum;
        }
        __syncthreads();
        prefix |= ((unsigned)s_sel) << shift;
        pmask  |= 0xFFu << shift;
        __syncthreads();
    }
    const int r = s_k;                 // #elements == threshold still needed
    const unsigned th = prefix;

    // strictly-greater set (exactly 1024 - r, unordered)
    if (tid == 0) { s_cnt = 0; s_run = 0; }
    __syncthreads();
    for (int i = tid; i < TOKENS; i += 1024) {
        unsigned v = vals[i];
        if (v > th) {
            unsigned p = atomicAdd(&s_cnt, 1u);
            cand[p] = ((unsigned long long)v << 32) | (unsigned)(~(unsigned)i);
        }
    }
    __syncthreads();
    const unsigned eqbase = (unsigned)(CAP - r);

    // equals in ascending-index order (stable tie-break = lax.top_k)
    for (int c = 0; c < TOKENS / 1024; c++) {
        int i = c * 1024 + tid;
        int flag = (vals[i] == th) ? 1 : 0;
        unsigned bal = __ballot_sync(0xffffffffu, flag);
        if (lane == 0) wsum[wid] = __popc(bal);
        __syncthreads();
        if (tid == 0) {
            unsigned a = s_run;
            for (int w = 0; w < 32; w++) { unsigned t = wsum[w]; wsum[w] = a; a += t; }
            s_run = a;
        }
        __syncthreads();
        if (flag) {
            unsigned rank = wsum[wid] + __popc(bal & ((1u << lane) - 1u));
            if (rank < (unsigned)r)
                cand[eqbase + rank] =
                    ((unsigned long long)th << 32) | (unsigned)(~(unsigned)i);
        }
        __syncthreads();
    }

    // bitonic sort 1024 keys DESCENDING (value desc, index asc via ~idx)
    for (unsigned kk = 2; kk <= 1024; kk <<= 1) {
        for (unsigned j = kk >> 1; j > 0; j >>= 1) {
            __syncthreads();
            unsigned i = (unsigned)tid, ixj = i ^ j;
            if (ixj > i) {
                unsigned long long a = cand[i], cc = cand[ixj];
                bool swp = ((i & kk) == 0) ? (a < cc) : (a > cc);
                if (swp) { cand[i] = cc; cand[ixj] = a; }
            }
        }
    }
    __syncthreads();

    unsigned long long key = cand[tid];
    unsigned m   = (unsigned)(key >> 32);
    unsigned idx = ~(unsigned)(key & 0xffffffffu);
    out_val[(size_t)e * CAP + tid] = mono_inv(m);
    out_idx[(size_t)e * CAP + tid] = (float)idx;
}

// ---------------- probs = fl( expf(l - M) / S ), vectorized x4 ------------
__global__ __launch_bounds__(256) void probs_kernel(
    const float* __restrict__ logits, float* __restrict__ probs)
{
    __shared__ float sM[64], sS[64];
    if (threadIdx.x < 64) {
        sM[threadIdx.x] = g_gmax[threadIdx.x];
        sS[threadIdx.x] = g_sum[threadIdx.x];
    }
    __syncthreads();
    int i4 = (blockIdx.x * 256 + threadIdx.x) * 4;   // grid covers 2M exactly
    float4 l = *(const float4*)(logits + i4);
    int e0 = i4 & 63;
    float4 p;
    p.x = __fdiv_rn(expf(__fsub_rn(l.x, sM[e0 + 0])), sS[e0 + 0]);
    p.y = __fdiv_rn(expf(__fsub_rn(l.y, sM[e0 + 1])), sS[e0 + 1]);
    p.z = __fdiv_rn(expf(__fsub_rn(l.z, sM[e0 + 2])), sS[e0 + 2]);
    p.w = __fdiv_rn(expf(__fsub_rn(l.w, sM[e0 + 3])), sS[e0 + 3]);
    *(float4*)(probs + i4) = p;
}

// ---------------- launch ----------------
extern "C" void kernel_launch(void* const* d_in, const int* in_sizes, int n_in,
                              void* d_out, int out_size)
{
    const float* x = (const float*)d_in[0];
    const float* W = (const float*)d_in[1];
    const float* b = (const float*)d_in[2];
    (void)in_sizes; (void)n_in; (void)out_size;

    float* out    = (float*)d_out;
    float* logits = out;                                  // 32768*64
    float* probs  = out + (size_t)TOKENS * NEXP;          // 32768*64
    float* ep     = out + 2 * (size_t)TOKENS * NEXP;      // 64*1024
    float* ei     = ep  + (size_t)NEXP * CAP;             // 64*1024

    cudaFuncSetAttribute(topk_kernel,
                         cudaFuncAttributeMaxDynamicSharedMemorySize, TOPK_SMEM);

    gemm_split2_kernel<<<GEMM_BLOCKS, 256>>>(x, W, b, logits);
    reduce_max_kernel<<<NEXP, 256>>>();
    topk_kernel<<<NEXP, 1024, TOPK_SMEM>>>(ep, ei);
    probs_kernel<<<(TOKENS * NEXP) / 1024, 256>>>(logits, probs);
}

// round 10
// speedup vs baseline: 1.3290x; 1.1335x over previous
#include <cuda_runtime.h>
#include <cstdint>
#include <math.h>

#define TOKENS 32768
#define DMODEL 1024
#define NEXP   64
#define CAP    1024
#define GEMM_BLOCKS 256   /* 32768 / 128 */

// ---------------- scratch (device globals, no allocation) ----------------
__device__ float g_pmax[GEMM_BLOCKS * NEXP];
__device__ float g_gmax[NEXP];
__device__ float g_sum[NEXP];
__device__ float g_lT[(size_t)NEXP * TOKENS];   // logits transposed [e][t], 8.4 MB

// ---------------- GEMM: logits = x @ W + b, 2-way block-split-K ----------
// Bitwise contract (== reference, verified R7): per output,
//   acc_lo = ascending-k FMA chain over k in [0,512)
//   acc_hi = ascending-k FMA chain over k in [512,1024)
//   logit  = fl(fl(acc_lo + acc_hi) + bias)
// BM=128, BN=64, BK=32; 256 threads; 8x4 micro-tile; LDS.128 A & B frags.
#define AS_PAD 36   /* floats per As row: 144B = 9*16B -> aligned, rotating banks */

__global__ __launch_bounds__(256, 2) void gemm_split2_kernel(
    const float* __restrict__ x, const float* __restrict__ W,
    const float* __restrict__ bias_in, float* __restrict__ logits)
{
    __shared__ float As[128 * AS_PAD];   // 18.4 KB
    __shared__ float Bs[32 * 64];        //  8.2 KB
    __shared__ float red[16 * 64];       //  4.0 KB

    const int tid = threadIdx.x;
    const int tx = tid & 15;       // n0 = tx*4
    const int ty = tid >> 4;       // m0 = ty*8
    const int m_base = blockIdx.x * 128;
    const float* xblk = x + (size_t)m_base * DMODEL;

    float acc[8][4];               // current half accumulators
    float accL[8][4];              // saved low-half result
#pragma unroll
    for (int i = 0; i < 8; i++)
#pragma unroll
        for (int j = 0; j < 4; j++) acc[i][j] = 0.0f;

#pragma unroll 1
    for (int half = 0; half < 2; half++) {
#pragma unroll 1
        for (int kt = 0; kt < 16; kt++) {
            const int kc = half * 512 + kt * 32;
            // x tile: 128 x 32 floats = 1024 float4, 4 per thread
#pragma unroll
            for (int j = 0; j < 4; j++) {
                int lin = tid + j * 256;          // float4 index
                int m = lin >> 3, c4 = lin & 7;   // 8 float4 per row
                float4 v = *(const float4*)(xblk + (size_t)m * DMODEL + kc + c4 * 4);
                *(float4*)&As[m * AS_PAD + c4 * 4] = v;
            }
            // W tile: 32 x 64 floats = 512 float4, 2 per thread
#pragma unroll
            for (int j = 0; j < 2; j++) {
                int lin = tid + j * 256;
                int kk = lin >> 4, n4 = lin & 15;
                *(float4*)&Bs[kk * 64 + n4 * 4] =
                    *(const float4*)(W + (size_t)(kc + kk) * NEXP + n4 * 4);
            }
            __syncthreads();

#pragma unroll
            for (int g = 0; g < 8; g++) {          // 4-kk groups
                float4 b0 = *(float4*)&Bs[(g * 4 + 0) * 64 + tx * 4];
                float4 b1 = *(float4*)&Bs[(g * 4 + 1) * 64 + tx * 4];
                float4 b2 = *(float4*)&Bs[(g * 4 + 2) * 64 + tx * 4];
                float4 b3 = *(float4*)&Bs[(g * 4 + 3) * 64 + tx * 4];
#pragma unroll
                for (int i = 0; i < 8; i++) {
                    float4 a = *(float4*)&As[(ty * 8 + i) * AS_PAD + g * 4];
                    // ascending kk within group: a.x, a.y, a.z, a.w
                    acc[i][0] = __fmaf_rn(a.x, b0.x, acc[i][0]);
                    acc[i][1] = __fmaf_rn(a.x, b0.y, acc[i][1]);
                    acc[i][2] = __fmaf_rn(a.x, b0.z, acc[i][2]);
                    acc[i][3] = __fmaf_rn(a.x, b0.w, acc[i][3]);
                    acc[i][0] = __fmaf_rn(a.y, b1.x, acc[i][0]);
                    acc[i][1] = __fmaf_rn(a.y, b1.y, acc[i][1]);
                    acc[i][2] = __fmaf_rn(a.y, b1.z, acc[i][2]);
                    acc[i][3] = __fmaf_rn(a.y, b1.w, acc[i][3]);
                    acc[i][0] = __fmaf_rn(a.z, b2.x, acc[i][0]);
                    acc[i][1] = __fmaf_rn(a.z, b2.y, acc[i][1]);
                    acc[i][2] = __fmaf_rn(a.z, b2.z, acc[i][2]);
                    acc[i][3] = __fmaf_rn(a.z, b2.w, acc[i][3]);
                    acc[i][0] = __fmaf_rn(a.w, b3.x, acc[i][0]);
                    acc[i][1] = __fmaf_rn(a.w, b3.y, acc[i][1]);
                    acc[i][2] = __fmaf_rn(a.w, b3.z, acc[i][2]);
                    acc[i][3] = __fmaf_rn(a.w, b3.w, acc[i][3]);
                }
            }
            __syncthreads();
        }
        if (half == 0) {
#pragma unroll
            for (int i = 0; i < 8; i++)
#pragma unroll
                for (int j = 0; j < 4; j++) { accL[i][j] = acc[i][j]; acc[i][j] = 0.0f; }
        }
    }

    // epilogue: fl(lo + hi) + bias  (exact R7 order)
    float4 bb = *(const float4*)(bias_in + tx * 4);
    float bias[4] = {bb.x, bb.y, bb.z, bb.w};
    float fin[8][4];
#pragma unroll
    for (int i = 0; i < 8; i++)
#pragma unroll
        for (int j = 0; j < 4; j++)
            fin[i][j] = __fadd_rn(__fadd_rn(accL[i][j], acc[i][j]), bias[j]);

    float cmax[4] = {-3.4e38f, -3.4e38f, -3.4e38f, -3.4e38f};
#pragma unroll
    for (int i = 0; i < 8; i++) {
        float4 o = make_float4(fin[i][0], fin[i][1], fin[i][2], fin[i][3]);
        *(float4*)(logits + (size_t)(m_base + ty * 8 + i) * NEXP + tx * 4) = o;
        cmax[0] = fmaxf(cmax[0], o.x); cmax[1] = fmaxf(cmax[1], o.y);
        cmax[2] = fmaxf(cmax[2], o.z); cmax[3] = fmaxf(cmax[3], o.w);
    }
    // transposed store: g_lT[n][m], two float4 along m per n
#pragma unroll
    for (int j = 0; j < 4; j++) {
        float4 t0 = make_float4(fin[0][j], fin[1][j], fin[2][j], fin[3][j]);
        float4 t1 = make_float4(fin[4][j], fin[5][j], fin[6][j], fin[7][j]);
        float* base = g_lT + (size_t)(tx * 4 + j) * TOKENS + m_base + ty * 8;
        *(float4*)(base + 0) = t0;
        *(float4*)(base + 4) = t1;
    }
#pragma unroll
    for (int j = 0; j < 4; j++) red[ty * 64 + tx * 4 + j] = cmax[j];
    __syncthreads();
    if (tid < 64) {
        float m = red[tid];
#pragma unroll
        for (int w = 1; w < 16; w++) m = fmaxf(m, red[w * 64 + tid]);
        g_pmax[(size_t)blockIdx.x * NEXP + tid] = m;
    }
}

// ---------------- fused: M + S + exact stable top-1024 per expert ---------
// M = fmax tree over per-block maxes (exact). u = expf(l - M); S = fl32(f64
// strided+tree sum, same order as R9 - bitwise identical); keys = fdiv(u,S).
__device__ __forceinline__ unsigned mono_fwd(float f) {
    unsigned u = __float_as_uint(f);
    return (u & 0x80000000u) ? ~u : (u | 0x80000000u);
}
__device__ __forceinline__ float mono_inv(unsigned m) {
    unsigned u = (m & 0x80000000u) ? (m ^ 0x80000000u) : ~m;
    return __uint_as_float(u);
}

#define TOPK_SMEM (131072 + 8192 + 8192 + 1024 + 128 + 1024)

__global__ __launch_bounds__(1024) void topk_kernel(
    float* __restrict__ out_val, float* __restrict__ out_idx)
{
    extern __shared__ unsigned char sm_raw[];
    float*              uval = (float*)sm_raw;                            // 32768 (aliased)
    unsigned*           vals = (unsigned*)sm_raw;                         // aliases uval
    unsigned long long* cand = (unsigned long long*)(sm_raw + 131072);    // 1024
    double*             dred = (double*)(sm_raw + 131072 + 8192);         // 1024
    unsigned*           hist = (unsigned*)(sm_raw + 131072 + 16384);      // 256
    unsigned*           wsum = (unsigned*)(sm_raw + 131072 + 16384 + 1024); // 32
    float*              fred = (float*)(sm_raw + 131072 + 16384 + 1024 + 128); // 256

    __shared__ int      s_sel;
    __shared__ int      s_k;
    __shared__ unsigned s_cnt;
    __shared__ unsigned s_run;
    __shared__ float    s_S;

    const int tid = threadIdx.x;
    const int e   = blockIdx.x;
    const int lane = tid & 31, wid = tid >> 5;

    // ---- M = exact column max from per-block maxes ----
    if (tid < GEMM_BLOCKS) fred[tid] = g_pmax[(size_t)tid * NEXP + e];
    if (tid == 0) s_k = CAP;
    __syncthreads();
    for (int st = GEMM_BLOCKS / 2; st > 0; st >>= 1) {
        if (tid < st) fred[tid] = fmaxf(fred[tid], fred[tid + st]);
        __syncthreads();
    }
    const float M = fred[0];
    if (tid == 0) g_gmax[e] = M;

    const float4* col = (const float4*)(g_lT + (size_t)e * TOKENS);

    // u = expf(l - M), accumulate f64 partial (same order as R9)
    double s = 0.0;
    for (int i = tid; i < TOKENS / 4; i += 1024) {
        float4 l = col[i];
        float u0 = expf(__fsub_rn(l.x, M));
        float u1 = expf(__fsub_rn(l.y, M));
        float u2 = expf(__fsub_rn(l.z, M));
        float u3 = expf(__fsub_rn(l.w, M));
        uval[4 * i + 0] = u0; uval[4 * i + 1] = u1;
        uval[4 * i + 2] = u2; uval[4 * i + 3] = u3;
        s += (double)u0; s += (double)u1; s += (double)u2; s += (double)u3;
    }
    dred[tid] = s;
    __syncthreads();
    for (int st = 512; st > 0; st >>= 1) {
        if (tid < st) dred[tid] += dred[tid + st];
        __syncthreads();
    }
    if (tid == 0) { s_S = (float)dred[0]; g_sum[e] = s_S; }
    __syncthreads();
    const float S = s_S;

    // convert u -> monotone key of prob = fdiv(u, S), in place
    for (int i = tid; i < TOKENS; i += 1024) {
        float u = uval[i];
        __syncwarp();
        vals[i] = mono_fwd(__fdiv_rn(u, S));
    }
    __syncthreads();

    // 4-pass MSB radix select -> exact fp32 threshold
    unsigned prefix = 0, pmask = 0;
#pragma unroll
    for (int pass = 0; pass < 4; pass++) {
        const int shift = 24 - 8 * pass;
        if (tid < 256) hist[tid] = 0;
        __syncthreads();
        for (int i = tid; i < TOKENS; i += 1024) {
            unsigned v = vals[i];
            if ((v & pmask) == prefix) atomicAdd(&hist[(v >> shift) & 255u], 1u);
        }
        __syncthreads();
        if (tid == 0) {
            int k = s_k; unsigned cum = 0; int bsel = 0;
            for (int bb = 255; bb >= 0; bb--) {
                unsigned c = hist[bb];
                if (cum + c >= (unsigned)k) { bsel = bb; break; }
                cum += c;
            }
            s_sel = bsel;
            s_k   = k - (int)cum;
        }
        __syncthreads();
        prefix |= ((unsigned)s_sel) << shift;
        pmask  |= 0xFFu << shift;
        __syncthreads();
    }
    const int r = s_k;                 // #elements == threshold still needed
    const unsigned th = prefix;

    // strictly-greater set (exactly 1024 - r, unordered)
    if (tid == 0) { s_cnt = 0; s_run = 0; }
    __syncthreads();
    for (int i = tid; i < TOKENS; i += 1024) {
        unsigned v = vals[i];
        if (v > th) {
            unsigned p = atomicAdd(&s_cnt, 1u);
            cand[p] = ((unsigned long long)v << 32) | (unsigned)(~(unsigned)i);
        }
    }
    __syncthreads();
    const unsigned eqbase = (unsigned)(CAP - r);

    // equals in ascending-index order (stable tie-break = lax.top_k)
    for (int c = 0; c < TOKENS / 1024; c++) {
        int i = c * 1024 + tid;
        int flag = (vals[i] == th) ? 1 : 0;
        unsigned bal = __ballot_sync(0xffffffffu, flag);
        if (lane == 0) wsum[wid] = __popc(bal);
        __syncthreads();
        if (tid == 0) {
            unsigned a = s_run;
            for (int w = 0; w < 32; w++) { unsigned t = wsum[w]; wsum[w] = a; a += t; }
            s_run = a;
        }
        __syncthreads();
        if (flag) {
            unsigned rank = wsum[wid] + __popc(bal & ((1u << lane) - 1u));
            if (rank < (unsigned)r)
                cand[eqbase + rank] =
                    ((unsigned long long)th << 32) | (unsigned)(~(unsigned)i);
        }
        __syncthreads();
    }

    // bitonic sort 1024 keys DESCENDING (value desc, index asc via ~idx)
    for (unsigned kk = 2; kk <= 1024; kk <<= 1) {
        for (unsigned j = kk >> 1; j > 0; j >>= 1) {
            __syncthreads();
            unsigned i = (unsigned)tid, ixj = i ^ j;
            if (ixj > i) {
                unsigned long long a = cand[i], cc = cand[ixj];
                bool swp = ((i & kk) == 0) ? (a < cc) : (a > cc);
                if (swp) { cand[i] = cc; cand[ixj] = a; }
            }
        }
    }
    __syncthreads();

    unsigned long long key = cand[tid];
    unsigned m   = (unsigned)(key >> 32);
    unsigned idx = ~(unsigned)(key & 0xffffffffu);
    out_val[(size_t)e * CAP + tid] = mono_inv(m);
    out_idx[(size_t)e * CAP + tid] = (float)idx;
}

// ---------------- probs = fl( expf(l - M) / S ), vectorized x4 ------------
__global__ __launch_bounds__(256) void probs_kernel(
    const float* __restrict__ logits, float* __restrict__ probs)
{
    __shared__ float sM[64], sS[64];
    if (threadIdx.x < 64) {
        sM[threadIdx.x] = g_gmax[threadIdx.x];
        sS[threadIdx.x] = g_sum[threadIdx.x];
    }
    __syncthreads();
    int i4 = (blockIdx.x * 256 + threadIdx.x) * 4;   // grid covers 2M exactly
    float4 l = *(const float4*)(logits + i4);
    int e0 = i4 & 63;
    float4 p;
    p.x = __fdiv_rn(expf(__fsub_rn(l.x, sM[e0 + 0])), sS[e0 + 0]);
    p.y = __fdiv_rn(expf(__fsub_rn(l.y, sM[e0 + 1])), sS[e0 + 1]);
    p.z = __fdiv_rn(expf(__fsub_rn(l.z, sM[e0 + 2])), sS[e0 + 2]);
    p.w = __fdiv_rn(expf(__fsub_rn(l.w, sM[e0 + 3])), sS[e0 + 3]);
    *(float4*)(probs + i4) = p;
}

// ---------------- launch ----------------
extern "C" void kernel_launch(void* const* d_in, const int* in_sizes, int n_in,
                              void* d_out, int out_size)
{
    const float* x = (const float*)d_in[0];
    const float* W = (const float*)d_in[1];
    const float* b = (const float*)d_in[2];
    (void)in_sizes; (void)n_in; (void)out_size;

    float* out    = (float*)d_out;
    float* logits = out;                                  // 32768*64
    float* probs  = out + (size_t)TOKENS * NEXP;          // 32768*64
    float* ep     = out + 2 * (size_t)TOKENS * NEXP;      // 64*1024
    float* ei     = ep  + (size_t)NEXP * CAP;             // 64*1024

    cudaFuncSetAttribute(topk_kernel,
                         cudaFuncAttributeMaxDynamicSharedMemorySize, TOPK_SMEM);

    gemm_split2_kernel<<<GEMM_BLOCKS, 256>>>(x, W, b, logits);
    topk_kernel<<<NEXP, 1024, TOPK_SMEM>>>(ep, ei);
    probs_kernel<<<(TOKENS * NEXP) / 1024, 256>>>(logits, probs);
}

// round 11
// speedup vs baseline: 1.5200x; 1.1437x over previous
#include <cuda_runtime.h>
#include <cstdint>
#include <math.h>

#define TOKENS 32768
#define DMODEL 1024
#define NEXP   64
#define CAP    1024
#define GEMM_BLOCKS 256   /* 32768 / 128 */

// ---------------- scratch (device globals, no allocation) ----------------
__device__ float g_pmax[GEMM_BLOCKS * NEXP];
__device__ float g_gmax[NEXP];
__device__ float g_sum[NEXP];
__device__ float g_lT[(size_t)NEXP * TOKENS];   // logits transposed [e][t], 8.4 MB

// ---------------- GEMM: logits = x @ W + b, 2-way block-split-K ----------
// Bitwise contract (== reference, verified R7/R10): per output,
//   acc_lo = ascending-k FMA chain over k in [0,512)
//   acc_hi = ascending-k FMA chain over k in [512,1024)
//   logit  = fl(fl(acc_lo + acc_hi) + bias)
#define AS_PAD 36

__global__ __launch_bounds__(256, 2) void gemm_split2_kernel(
    const float* __restrict__ x, const float* __restrict__ W,
    const float* __restrict__ bias_in, float* __restrict__ logits)
{
    __shared__ float As[128 * AS_PAD];
    __shared__ float Bs[32 * 64];
    __shared__ float red[16 * 64];

    const int tid = threadIdx.x;
    const int tx = tid & 15;
    const int ty = tid >> 4;
    const int m_base = blockIdx.x * 128;
    const float* xblk = x + (size_t)m_base * DMODEL;

    float acc[8][4];
    float accL[8][4];
#pragma unroll
    for (int i = 0; i < 8; i++)
#pragma unroll
        for (int j = 0; j < 4; j++) acc[i][j] = 0.0f;

#pragma unroll 1
    for (int half = 0; half < 2; half++) {
#pragma unroll 1
        for (int kt = 0; kt < 16; kt++) {
            const int kc = half * 512 + kt * 32;
#pragma unroll
            for (int j = 0; j < 4; j++) {
                int lin = tid + j * 256;
                int m = lin >> 3, c4 = lin & 7;
                float4 v = *(const float4*)(xblk + (size_t)m * DMODEL + kc + c4 * 4);
                *(float4*)&As[m * AS_PAD + c4 * 4] = v;
            }
#pragma unroll
            for (int j = 0; j < 2; j++) {
                int lin = tid + j * 256;
                int kk = lin >> 4, n4 = lin & 15;
                *(float4*)&Bs[kk * 64 + n4 * 4] =
                    *(const float4*)(W + (size_t)(kc + kk) * NEXP + n4 * 4);
            }
            __syncthreads();

#pragma unroll
            for (int g = 0; g < 8; g++) {
                float4 b0 = *(float4*)&Bs[(g * 4 + 0) * 64 + tx * 4];
                float4 b1 = *(float4*)&Bs[(g * 4 + 1) * 64 + tx * 4];
                float4 b2 = *(float4*)&Bs[(g * 4 + 2) * 64 + tx * 4];
                float4 b3 = *(float4*)&Bs[(g * 4 + 3) * 64 + tx * 4];
#pragma unroll
                for (int i = 0; i < 8; i++) {
                    float4 a = *(float4*)&As[(ty * 8 + i) * AS_PAD + g * 4];
                    acc[i][0] = __fmaf_rn(a.x, b0.x, acc[i][0]);
                    acc[i][1] = __fmaf_rn(a.x, b0.y, acc[i][1]);
                    acc[i][2] = __fmaf_rn(a.x, b0.z, acc[i][2]);
                    acc[i][3] = __fmaf_rn(a.x, b0.w, acc[i][3]);
                    acc[i][0] = __fmaf_rn(a.y, b1.x, acc[i][0]);
                    acc[i][1] = __fmaf_rn(a.y, b1.y, acc[i][1]);
                    acc[i][2] = __fmaf_rn(a.y, b1.z, acc[i][2]);
                    acc[i][3] = __fmaf_rn(a.y, b1.w, acc[i][3]);
                    acc[i][0] = __fmaf_rn(a.z, b2.x, acc[i][0]);
                    acc[i][1] = __fmaf_rn(a.z, b2.y, acc[i][1]);
                    acc[i][2] = __fmaf_rn(a.z, b2.z, acc[i][2]);
                    acc[i][3] = __fmaf_rn(a.z, b2.w, acc[i][3]);
                    acc[i][0] = __fmaf_rn(a.w, b3.x, acc[i][0]);
                    acc[i][1] = __fmaf_rn(a.w, b3.y, acc[i][1]);
                    acc[i][2] = __fmaf_rn(a.w, b3.z, acc[i][2]);
                    acc[i][3] = __fmaf_rn(a.w, b3.w, acc[i][3]);
                }
            }
            __syncthreads();
        }
        if (half == 0) {
#pragma unroll
            for (int i = 0; i < 8; i++)
#pragma unroll
                for (int j = 0; j < 4; j++) { accL[i][j] = acc[i][j]; acc[i][j] = 0.0f; }
        }
    }

    float4 bb = *(const float4*)(bias_in + tx * 4);
    float bias[4] = {bb.x, bb.y, bb.z, bb.w};
    float fin[8][4];
#pragma unroll
    for (int i = 0; i < 8; i++)
#pragma unroll
        for (int j = 0; j < 4; j++)
            fin[i][j] = __fadd_rn(__fadd_rn(accL[i][j], acc[i][j]), bias[j]);

    float cmax[4] = {-3.4e38f, -3.4e38f, -3.4e38f, -3.4e38f};
#pragma unroll
    for (int i = 0; i < 8; i++) {
        float4 o = make_float4(fin[i][0], fin[i][1], fin[i][2], fin[i][3]);
        *(float4*)(logits + (size_t)(m_base + ty * 8 + i) * NEXP + tx * 4) = o;
        cmax[0] = fmaxf(cmax[0], o.x); cmax[1] = fmaxf(cmax[1], o.y);
        cmax[2] = fmaxf(cmax[2], o.z); cmax[3] = fmaxf(cmax[3], o.w);
    }
#pragma unroll
    for (int j = 0; j < 4; j++) {
        float4 t0 = make_float4(fin[0][j], fin[1][j], fin[2][j], fin[3][j]);
        float4 t1 = make_float4(fin[4][j], fin[5][j], fin[6][j], fin[7][j]);
        float* base = g_lT + (size_t)(tx * 4 + j) * TOKENS + m_base + ty * 8;
        *(float4*)(base + 0) = t0;
        *(float4*)(base + 4) = t1;
    }
#pragma unroll
    for (int j = 0; j < 4; j++) red[ty * 64 + tx * 4 + j] = cmax[j];
    __syncthreads();
    if (tid < 64) {
        float m = red[tid];
#pragma unroll
        for (int w = 1; w < 16; w++) m = fmaxf(m, red[w * 64 + tid]);
        g_pmax[(size_t)blockIdx.x * NEXP + tid] = m;
    }
}

// ---------------- fused: M + S + exact stable top-1024 per expert ---------
__device__ __forceinline__ unsigned mono_fwd(float f) {
    unsigned u = __float_as_uint(f);
    return (u & 0x80000000u) ? ~u : (u | 0x80000000u);
}
__device__ __forceinline__ float mono_inv(unsigned m) {
    unsigned u = (m & 0x80000000u) ? (m ^ 0x80000000u) : ~m;
    return __uint_as_float(u);
}

// smem layout offsets (bytes)
#define OFF_VALS  0
#define OFF_CAND  131072
#define OFF_DRED  (131072 + 8192)
#define OFF_HIST  (131072 + 16384)
#define OFF_WTMP  (131072 + 16384 + 8192)
#define OFF_FRED  (131072 + 16384 + 8192 + 128)
#define TOPK_SMEM (131072 + 16384 + 8192 + 128 + 1024)

// descending bucket select over 2048 bins: find first bin from the TOP with
// cumulative count >= k. Writes *s_sel (bin) and *s_rem (k - cum_above).
__device__ __forceinline__ void block_select2048(
    unsigned* hist, unsigned* wtmp, int k, int tid,
    volatile int* s_sel, volatile int* s_rem)
{
    const int lane = tid & 31, wid = tid >> 5;
    unsigned a = hist[2047 - 2 * tid];
    unsigned b = hist[2047 - (2 * tid + 1)];
    unsigned s = a + b, v = s;
#pragma unroll
    for (int o = 1; o < 32; o <<= 1) {
        unsigned n = __shfl_up_sync(0xffffffffu, v, o);
        if (lane >= o) v += n;
    }
    if (lane == 31) wtmp[wid] = v;
    __syncthreads();
    if (wid == 0) {
        unsigned w = wtmp[lane], vv = w;
#pragma unroll
        for (int o = 1; o < 32; o <<= 1) {
            unsigned n = __shfl_up_sync(0xffffffffu, vv, o);
            if (lane >= o) vv += n;
        }
        wtmp[lane] = vv - w;   // exclusive warp base
    }
    __syncthreads();
    unsigned ex = wtmp[wid] + (v - s);      // count in bins above slot0's bin
    unsigned uk = (unsigned)k;
    if (ex < uk && uk <= ex + a) { *s_sel = 2047 - 2 * tid; *s_rem = (int)(uk - ex); }
    unsigned e1 = ex + a;
    if (e1 < uk && uk <= e1 + b) { *s_sel = 2046 - 2 * tid; *s_rem = (int)(uk - e1); }
    __syncthreads();
}

__global__ __launch_bounds__(1024) void topk_kernel(
    float* __restrict__ out_val, float* __restrict__ out_idx)
{
    extern __shared__ unsigned char sm_raw[];
    float*              uval = (float*)(sm_raw + OFF_VALS);     // 32768 floats
    unsigned*           vals = (unsigned*)(sm_raw + OFF_VALS);  // aliases uval
    unsigned long long* cand = (unsigned long long*)(sm_raw + OFF_CAND); // 1024
    double*             dred = (double*)(sm_raw + OFF_DRED);    // 1024
    unsigned*           hist = (unsigned*)(sm_raw + OFF_HIST);  // 2048
    int*                eqbuf = (int*)(sm_raw + OFF_HIST);      // aliases hist
    unsigned*           wtmp = (unsigned*)(sm_raw + OFF_WTMP);  // 32
    float*              fred = (float*)(sm_raw + OFF_FRED);     // 256

    __shared__ volatile int s_sel;
    __shared__ volatile int s_k;
    __shared__ unsigned     s_cnt;
    __shared__ unsigned     s_eqc;
    __shared__ float        s_S;

    const int tid = threadIdx.x;
    const int e   = blockIdx.x;

    // ---- M = exact column max from per-block maxes ----
    if (tid < GEMM_BLOCKS) fred[tid] = g_pmax[(size_t)tid * NEXP + e];
    __syncthreads();
    for (int st = GEMM_BLOCKS / 2; st > 0; st >>= 1) {
        if (tid < st) fred[tid] = fmaxf(fred[tid], fred[tid + st]);
        __syncthreads();
    }
    const float M = fred[0];
    if (tid == 0) g_gmax[e] = M;

    const float4* col = (const float4*)(g_lT + (size_t)e * TOKENS);

    // ---- u = expf(l - M); S = fl32(f64 strided+tree sum) (order == R10) ----
    double s = 0.0;
    for (int i = tid; i < TOKENS / 4; i += 1024) {
        float4 l = col[i];
        float u0 = expf(__fsub_rn(l.x, M));
        float u1 = expf(__fsub_rn(l.y, M));
        float u2 = expf(__fsub_rn(l.z, M));
        float u3 = expf(__fsub_rn(l.w, M));
        uval[4 * i + 0] = u0; uval[4 * i + 1] = u1;
        uval[4 * i + 2] = u2; uval[4 * i + 3] = u3;
        s += (double)u0; s += (double)u1; s += (double)u2; s += (double)u3;
    }
    dred[tid] = s;
    __syncthreads();
    for (int st = 512; st > 0; st >>= 1) {
        if (tid < st) dred[tid] += dred[tid + st];
        __syncthreads();
    }
    if (tid == 0) { s_S = (float)dred[0]; g_sum[e] = s_S; }
    __syncthreads();
    const float S = s_S;

    // ---- keys = mono(fdiv(u, S)) in place ----
    for (int i = tid; i < TOKENS; i += 1024)
        vals[i] = mono_fwd(__fdiv_rn(uval[i], S));
    __syncthreads();

    // ---- 3-pass radix select (11/11/10 bits), parallel suffix scan ----
    // pass 1: bins = v >> 21
    hist[tid] = 0; hist[tid + 1024] = 0;
    __syncthreads();
    for (int i = tid; i < TOKENS; i += 1024)
        atomicAdd(&hist[vals[i] >> 21], 1u);
    __syncthreads();
    block_select2048(hist, wtmp, CAP, tid, &s_sel, &s_k);
    const unsigned pre11 = (unsigned)s_sel;
    int krem = s_k;
    __syncthreads();

    // pass 2: among (v>>21)==pre11, bins = (v>>10)&0x7FF
    hist[tid] = 0; hist[tid + 1024] = 0;
    __syncthreads();
    for (int i = tid; i < TOKENS; i += 1024) {
        unsigned v = vals[i];
        if ((v >> 21) == pre11) atomicAdd(&hist[(v >> 10) & 0x7FFu], 1u);
    }
    __syncthreads();
    block_select2048(hist, wtmp, krem, tid, &s_sel, &s_k);
    const unsigned pre22 = (pre11 << 11) | (unsigned)s_sel;
    krem = s_k;
    __syncthreads();

    // pass 3: among (v>>10)==pre22, bins = v & 0x3FF (1024 real + 1024 zero pad)
    hist[tid] = 0; hist[tid + 1024] = 0;
    __syncthreads();
    for (int i = tid; i < TOKENS; i += 1024) {
        unsigned v = vals[i];
        if ((v >> 10) == pre22) atomicAdd(&hist[v & 0x3FFu], 1u);
    }
    __syncthreads();
    block_select2048(hist, wtmp, krem, tid, &s_sel, &s_k);
    const unsigned th = (pre22 << 10) | (unsigned)s_sel;
    const int r = s_k;                       // 1 <= r <= CAP
    __syncthreads();

    // ---- fused collect: greater -> cand, equal -> eqbuf (aliases hist) ----
    if (tid == 0) { s_cnt = 0; s_eqc = 0; }
    __syncthreads();
    for (int i = tid; i < TOKENS; i += 1024) {
        unsigned v = vals[i];
        if (v > th) {
            unsigned p = atomicAdd(&s_cnt, 1u);
            cand[p] = ((unsigned long long)v << 32) | (unsigned)(~(unsigned)i);
        } else if (v == th) {
            unsigned p = atomicAdd(&s_eqc, 1u);
            if (p < 2048u) eqbuf[p] = i;
        }
    }
    __syncthreads();
    const int cnt_eq = (int)s_eqc;
    const int eqbase = CAP - r;

    if (cnt_eq == r) {
        // all equals selected; final sort orders them by index
        for (int l = tid; l < r; l += 1024)
            cand[eqbase + l] =
                ((unsigned long long)th << 32) | (unsigned)(~(unsigned)eqbuf[l]);
    } else if (cnt_eq <= 2048) {
        // r smallest indices among cnt_eq equals, by parallel rank
        for (int l = tid; l < cnt_eq; l += 1024) {
            int idx = eqbuf[l];
            int rank = 0;
            for (int m = 0; m < cnt_eq; m++) rank += (eqbuf[m] < idx) ? 1 : 0;
            if (rank < r)
                cand[eqbase + rank] =
                    ((unsigned long long)th << 32) | (unsigned)(~(unsigned)idx);
        }
    } else {
        // pathological fallback (never expected): exact rank by full scan
        for (int i = tid; i < TOKENS; i += 1024) {
            if (vals[i] == th) {
                int rank = 0;
                for (int j = 0; j < i; j++) rank += (vals[j] == th) ? 1 : 0;
                if (rank < r)
                    cand[eqbase + rank] =
                        ((unsigned long long)th << 32) | (unsigned)(~(unsigned)i);
            }
        }
    }
    __syncthreads();

    // ---- hybrid bitonic sort: 1024 keys, DESC (val desc, idx asc) ----
    unsigned long long key = cand[tid];
#pragma unroll 1
    for (unsigned kk = 2; kk <= 1024; kk <<= 1) {
        unsigned j = kk >> 1;
        for (; j >= 32; j >>= 1) {
            cand[tid] = key;
            __syncthreads();
            unsigned long long p = cand[tid ^ j];
            bool up = ((tid & kk) == 0);
            bool lowr = ((tid & j) == 0);
            bool takeMax = (up == lowr);
            key = takeMax ? (key > p ? key : p) : (key > p ? p : key);
            __syncthreads();
        }
        for (; j >= 1; j >>= 1) {
            unsigned long long p = __shfl_xor_sync(0xffffffffu, key, j);
            bool up = ((tid & kk) == 0);
            bool lowr = ((tid & j) == 0);
            bool takeMax = (up == lowr);
            key = takeMax ? (key > p ? key : p) : (key > p ? p : key);
        }
    }

    unsigned m   = (unsigned)(key >> 32);
    unsigned idx = ~(unsigned)(key & 0xffffffffu);
    out_val[(size_t)e * CAP + tid] = mono_inv(m);
    out_idx[(size_t)e * CAP + tid] = (float)idx;
}

// ---------------- probs = fl( expf(l - M) / S ), vectorized x4 ------------
__global__ __launch_bounds__(256) void probs_kernel(
    const float* __restrict__ logits, float* __restrict__ probs)
{
    __shared__ float sM[64], sS[64];
    if (threadIdx.x < 64) {
        sM[threadIdx.x] = g_gmax[threadIdx.x];
        sS[threadIdx.x] = g_sum[threadIdx.x];
    }
    __syncthreads();
    int i4 = (blockIdx.x * 256 + threadIdx.x) * 4;
    float4 l = *(const float4*)(logits + i4);
    int e0 = i4 & 63;
    float4 p;
    p.x = __fdiv_rn(expf(__fsub_rn(l.x, sM[e0 + 0])), sS[e0 + 0]);
    p.y = __fdiv_rn(expf(__fsub_rn(l.y, sM[e0 + 1])), sS[e0 + 1]);
    p.z = __fdiv_rn(expf(__fsub_rn(l.z, sM[e0 + 2])), sS[e0 + 2]);
    p.w = __fdiv_rn(expf(__fsub_rn(l.w, sM[e0 + 3])), sS[e0 + 3]);
    *(float4*)(probs + i4) = p;
}

// ---------------- launch ----------------
extern "C" void kernel_launch(void* const* d_in, const int* in_sizes, int n_in,
                              void* d_out, int out_size)
{
    const float* x = (const float*)d_in[0];
    const float* W = (const float*)d_in[1];
    const float* b = (const float*)d_in[2];
    (void)in_sizes; (void)n_in; (void)out_size;

    float* out    = (float*)d_out;
    float* logits = out;                                  // 32768*64
    float* probs  = out + (size_t)TOKENS * NEXP;          // 32768*64
    float* ep     = out + 2 * (size_t)TOKENS * NEXP;      // 64*1024
    float* ei     = ep  + (size_t)NEXP * CAP;             // 64*1024

    cudaFuncSetAttribute(topk_kernel,
                         cudaFuncAttributeMaxDynamicSharedMemorySize, TOPK_SMEM);

    gemm_split2_kernel<<<GEMM_BLOCKS, 256>>>(x, W, b, logits);
    topk_kernel<<<NEXP, 1024, TOPK_SMEM>>>(ep, ei);
    probs_kernel<<<(TOKENS * NEXP) / 1024, 256>>>(logits, probs);
}

// round 12
// speedup vs baseline: 1.7173x; 1.1297x over previous
#include <cuda_runtime.h>
#include <cstdint>
#include <math.h>

#define TOKENS 32768
#define DMODEL 1024
#define NEXP   64
#define CAP    1024
#define GEMM_BLOCKS 256   /* 32768 / 128 */

// ---------------- scratch (device globals, no allocation) ----------------
__device__ float g_pmax[GEMM_BLOCKS * NEXP];
__device__ float g_gmax[NEXP];
__device__ float g_sum[NEXP];
__device__ float g_lT[(size_t)NEXP * TOKENS];   // logits transposed [e][t], 8.4 MB

__device__ __forceinline__ void cp_async16(void* sdst, const void* gsrc) {
    unsigned s = (unsigned)__cvta_generic_to_shared(sdst);
    asm volatile("cp.async.cg.shared.global [%0], [%1], 16;" :: "r"(s), "l"(gsrc));
}

// ---------------- GEMM: logits = x @ W + b, 2-way block-split-K ----------
// Bitwise contract (== reference, verified R7/R10/R11): per output,
//   acc_lo = ascending-k FMA chain over k in [0,512)
//   acc_hi = ascending-k FMA chain over k in [512,1024)
//   logit  = fl(fl(acc_lo + acc_hi) + bias)
// BM=128, BN=64, BK=32; 256 threads; 8x4 micro-tile; cp.async double buffer.
#define AS_PAD 36
#define GEMM_SMEM ((2 * 128 * AS_PAD + 2 * 2048 + 1024) * 4)   /* 57344 B */

__global__ __launch_bounds__(256, 2) void gemm_split2_kernel(
    const float* __restrict__ x, const float* __restrict__ W,
    const float* __restrict__ bias_in, float* __restrict__ logits)
{
    extern __shared__ float sm_f[];
    float* Asm = sm_f;                       // [2][128*AS_PAD]
    float* Bsm = sm_f + 2 * 128 * AS_PAD;    // [2][2048]
    float* red = Bsm + 2 * 2048;             // [1024]

    const int tid = threadIdx.x;
    const int tx = tid & 15;
    const int ty = tid >> 4;
    const int m_base = blockIdx.x * 128;
    const float* xblk = x + (size_t)m_base * DMODEL;

    // per-thread load coords (fixed)
    const int am0 = tid >> 3, ac0 = tid & 7;          // + j*32 rows
    const int bk0 = tid >> 4, bn0 = tid & 15;         // + j*16 rows

    float acc[8][4];
    float accL[8][4];
#pragma unroll
    for (int i = 0; i < 8; i++)
#pragma unroll
        for (int j = 0; j < 4; j++) acc[i][j] = 0.0f;

    // issue tile 0
    {
        float* Ab = Asm; float* Bb = Bsm;
#pragma unroll
        for (int j = 0; j < 4; j++) {
            int m = am0 + j * 32;
            cp_async16(&Ab[m * AS_PAD + ac0 * 4],
                       xblk + (size_t)m * DMODEL + ac0 * 4);
        }
#pragma unroll
        for (int j = 0; j < 2; j++) {
            int kk = bk0 + j * 16;
            cp_async16(&Bb[kk * 64 + bn0 * 4],
                       W + (size_t)kk * NEXP + bn0 * 4);
        }
        asm volatile("cp.async.commit_group;");
    }

#pragma unroll 1
    for (int i = 0; i < 32; i++) {
        if (i < 31) {
            const int kc = (i + 1) * 32;
            float* Ab = Asm + ((i + 1) & 1) * (128 * AS_PAD);
            float* Bb = Bsm + ((i + 1) & 1) * 2048;
#pragma unroll
            for (int j = 0; j < 4; j++) {
                int m = am0 + j * 32;
                cp_async16(&Ab[m * AS_PAD + ac0 * 4],
                           xblk + (size_t)m * DMODEL + kc + ac0 * 4);
            }
#pragma unroll
            for (int j = 0; j < 2; j++) {
                int kk = bk0 + j * 16;
                cp_async16(&Bb[kk * 64 + bn0 * 4],
                           W + (size_t)(kc + kk) * NEXP + bn0 * 4);
            }
            asm volatile("cp.async.commit_group;");
            asm volatile("cp.async.wait_group 1;" ::: "memory");
        } else {
            asm volatile("cp.async.wait_group 0;" ::: "memory");
        }
        __syncthreads();

        const float* Ab = Asm + (i & 1) * (128 * AS_PAD);
        const float* Bb = Bsm + (i & 1) * 2048;
#pragma unroll
        for (int g = 0; g < 8; g++) {
            float4 b0 = *(const float4*)&Bb[(g * 4 + 0) * 64 + tx * 4];
            float4 b1 = *(const float4*)&Bb[(g * 4 + 1) * 64 + tx * 4];
            float4 b2 = *(const float4*)&Bb[(g * 4 + 2) * 64 + tx * 4];
            float4 b3 = *(const float4*)&Bb[(g * 4 + 3) * 64 + tx * 4];
#pragma unroll
            for (int ii = 0; ii < 8; ii++) {
                float4 a = *(const float4*)&Ab[(ty * 8 + ii) * AS_PAD + g * 4];
                acc[ii][0] = __fmaf_rn(a.x, b0.x, acc[ii][0]);
                acc[ii][1] = __fmaf_rn(a.x, b0.y, acc[ii][1]);
                acc[ii][2] = __fmaf_rn(a.x, b0.z, acc[ii][2]);
                acc[ii][3] = __fmaf_rn(a.x, b0.w, acc[ii][3]);
                acc[ii][0] = __fmaf_rn(a.y, b1.x, acc[ii][0]);
                acc[ii][1] = __fmaf_rn(a.y, b1.y, acc[ii][1]);
                acc[ii][2] = __fmaf_rn(a.y, b1.z, acc[ii][2]);
                acc[ii][3] = __fmaf_rn(a.y, b1.w, acc[ii][3]);
                acc[ii][0] = __fmaf_rn(a.z, b2.x, acc[ii][0]);
                acc[ii][1] = __fmaf_rn(a.z, b2.y, acc[ii][1]);
                acc[ii][2] = __fmaf_rn(a.z, b2.z, acc[ii][2]);
                acc[ii][3] = __fmaf_rn(a.z, b2.w, acc[ii][3]);
                acc[ii][0] = __fmaf_rn(a.w, b3.x, acc[ii][0]);
                acc[ii][1] = __fmaf_rn(a.w, b3.y, acc[ii][1]);
                acc[ii][2] = __fmaf_rn(a.w, b3.z, acc[ii][2]);
                acc[ii][3] = __fmaf_rn(a.w, b3.w, acc[ii][3]);
            }
        }
        __syncthreads();

        if (i == 15) {
#pragma unroll
            for (int ii = 0; ii < 8; ii++)
#pragma unroll
                for (int j = 0; j < 4; j++) { accL[ii][j] = acc[ii][j]; acc[ii][j] = 0.0f; }
        }
    }

    // epilogue: fl(lo + hi) + bias  (exact R7 order)
    float4 bb = *(const float4*)(bias_in + tx * 4);
    float bias[4] = {bb.x, bb.y, bb.z, bb.w};
    float fin[8][4];
#pragma unroll
    for (int i = 0; i < 8; i++)
#pragma unroll
        for (int j = 0; j < 4; j++)
            fin[i][j] = __fadd_rn(__fadd_rn(accL[i][j], acc[i][j]), bias[j]);

    float cmax[4] = {-3.4e38f, -3.4e38f, -3.4e38f, -3.4e38f};
#pragma unroll
    for (int i = 0; i < 8; i++) {
        float4 o = make_float4(fin[i][0], fin[i][1], fin[i][2], fin[i][3]);
        *(float4*)(logits + (size_t)(m_base + ty * 8 + i) * NEXP + tx * 4) = o;
        cmax[0] = fmaxf(cmax[0], o.x); cmax[1] = fmaxf(cmax[1], o.y);
        cmax[2] = fmaxf(cmax[2], o.z); cmax[3] = fmaxf(cmax[3], o.w);
    }
#pragma unroll
    for (int j = 0; j < 4; j++) {
        float4 t0 = make_float4(fin[0][j], fin[1][j], fin[2][j], fin[3][j]);
        float4 t1 = make_float4(fin[4][j], fin[5][j], fin[6][j], fin[7][j]);
        float* base = g_lT + (size_t)(tx * 4 + j) * TOKENS + m_base + ty * 8;
        *(float4*)(base + 0) = t0;
        *(float4*)(base + 4) = t1;
    }
#pragma unroll
    for (int j = 0; j < 4; j++) red[ty * 64 + tx * 4 + j] = cmax[j];
    __syncthreads();
    if (tid < 64) {
        float m = red[tid];
#pragma unroll
        for (int w = 1; w < 16; w++) m = fmaxf(m, red[w * 64 + tid]);
        g_pmax[(size_t)blockIdx.x * NEXP + tid] = m;
    }
}

// ---------------- fused: M + S + exact stable top-1024 per expert ---------
__device__ __forceinline__ unsigned mono_fwd(float f) {
    unsigned u = __float_as_uint(f);
    return (u & 0x80000000u) ? ~u : (u | 0x80000000u);
}
__device__ __forceinline__ float mono_inv(unsigned m) {
    unsigned u = (m & 0x80000000u) ? (m ^ 0x80000000u) : ~m;
    return __uint_as_float(u);
}

// smem layout offsets (bytes)
#define OFF_VALS  0
#define OFF_CAND  131072
#define OFF_DRED  (131072 + 8192)
#define OFF_HIST  (131072 + 16384)
#define OFF_WTMP  (131072 + 16384 + 8192)
#define OFF_FRED  (131072 + 16384 + 8192 + 128)
#define OFF_CBUF  (131072 + 16384 + 8192 + 128 + 1024)
#define CBUF_N    8192
#define TOPK_SMEM (OFF_CBUF + CBUF_N * 4)

// descending bucket select over 2048 bins: first bin from TOP with cum >= k.
__device__ __forceinline__ void block_select2048(
    unsigned* hist, unsigned* wtmp, int k, int tid,
    volatile int* s_sel, volatile int* s_rem)
{
    const int lane = tid & 31, wid = tid >> 5;
    unsigned a = hist[2047 - 2 * tid];
    unsigned b = hist[2047 - (2 * tid + 1)];
    unsigned s = a + b, v = s;
#pragma unroll
    for (int o = 1; o < 32; o <<= 1) {
        unsigned n = __shfl_up_sync(0xffffffffu, v, o);
        if (lane >= o) v += n;
    }
    if (lane == 31) wtmp[wid] = v;
    __syncthreads();
    if (wid == 0) {
        unsigned w = wtmp[lane], vv = w;
#pragma unroll
        for (int o = 1; o < 32; o <<= 1) {
            unsigned n = __shfl_up_sync(0xffffffffu, vv, o);
            if (lane >= o) vv += n;
        }
        wtmp[lane] = vv - w;
    }
    __syncthreads();
    unsigned ex = wtmp[wid] + (v - s);
    unsigned uk = (unsigned)k;
    if (ex < uk && uk <= ex + a) { *s_sel = 2047 - 2 * tid; *s_rem = (int)(uk - ex); }
    unsigned e1 = ex + a;
    if (e1 < uk && uk <= e1 + b) { *s_sel = 2046 - 2 * tid; *s_rem = (int)(uk - e1); }
    __syncthreads();
}

__global__ __launch_bounds__(1024) void topk_kernel(
    float* __restrict__ out_val, float* __restrict__ out_idx)
{
    extern __shared__ unsigned char sm_raw[];
    float*              uval = (float*)(sm_raw + OFF_VALS);
    unsigned*           vals = (unsigned*)(sm_raw + OFF_VALS);
    unsigned long long* cand = (unsigned long long*)(sm_raw + OFF_CAND);
    double*             dred = (double*)(sm_raw + OFF_DRED);
    unsigned*           hist = (unsigned*)(sm_raw + OFF_HIST);
    int*                eqbuf = (int*)(sm_raw + OFF_HIST);
    unsigned*           wtmp = (unsigned*)(sm_raw + OFF_WTMP);
    float*              fred = (float*)(sm_raw + OFF_FRED);
    unsigned*           cbuf = (unsigned*)(sm_raw + OFF_CBUF);

    __shared__ volatile int s_sel;
    __shared__ volatile int s_k;
    __shared__ unsigned     s_cnt;
    __shared__ unsigned     s_eqc;
    __shared__ unsigned     s_cb;
    __shared__ float        s_S;

    const int tid = threadIdx.x;
    const int e   = blockIdx.x;

    // ---- M = exact column max from per-block maxes ----
    if (tid < GEMM_BLOCKS) fred[tid] = g_pmax[(size_t)tid * NEXP + e];
    __syncthreads();
    for (int st = GEMM_BLOCKS / 2; st > 0; st >>= 1) {
        if (tid < st) fred[tid] = fmaxf(fred[tid], fred[tid + st]);
        __syncthreads();
    }
    const float M = fred[0];
    if (tid == 0) g_gmax[e] = M;

    const float4* col = (const float4*)(g_lT + (size_t)e * TOKENS);

    // ---- u = expf(l - M); S = fl32(f64 strided+tree sum) (order == R10) ----
    double s = 0.0;
    for (int i = tid; i < TOKENS / 4; i += 1024) {
        float4 l = col[i];
        float u0 = expf(__fsub_rn(l.x, M));
        float u1 = expf(__fsub_rn(l.y, M));
        float u2 = expf(__fsub_rn(l.z, M));
        float u3 = expf(__fsub_rn(l.w, M));
        uval[4 * i + 0] = u0; uval[4 * i + 1] = u1;
        uval[4 * i + 2] = u2; uval[4 * i + 3] = u3;
        s += (double)u0; s += (double)u1; s += (double)u2; s += (double)u3;
    }
    dred[tid] = s;
    __syncthreads();
    for (int st = 512; st > 0; st >>= 1) {
        if (tid < st) dred[tid] += dred[tid + st];
        __syncthreads();
    }
    if (tid == 0) { s_S = (float)dred[0]; g_sum[e] = s_S; }
    __syncthreads();
    const float S = s_S;

    // ---- keys = mono(fdiv(u, S)) in place ----
    for (int i = tid; i < TOKENS; i += 1024)
        vals[i] = mono_fwd(__fdiv_rn(uval[i], S));
    __syncthreads();

    // ---- pass 1: bins = v >> 21 ----
    hist[tid] = 0; hist[tid + 1024] = 0;
    __syncthreads();
    for (int i = tid; i < TOKENS; i += 1024)
        atomicAdd(&hist[vals[i] >> 21], 1u);
    __syncthreads();
    block_select2048(hist, wtmp, CAP, tid, &s_sel, &s_k);
    const unsigned pre11 = (unsigned)s_sel;
    int krem = s_k;
    __syncthreads();

    // ---- compact pass-1 matches into cbuf ----
    if (tid == 0) s_cb = 0;
    __syncthreads();
    for (int i = tid; i < TOKENS; i += 1024) {
        unsigned v = vals[i];
        if ((v >> 21) == pre11) {
            unsigned p = atomicAdd(&s_cb, 1u);
            if (p < CBUF_N) cbuf[p] = v;
        }
    }
    __syncthreads();
    const bool usec = (s_cb <= CBUF_N);
    const int  ncb  = usec ? (int)s_cb : 0;

    // ---- pass 2: among (v>>21)==pre11, bins = (v>>10)&0x7FF ----
    hist[tid] = 0; hist[tid + 1024] = 0;
    __syncthreads();
    if (usec) {
        for (int l = tid; l < ncb; l += 1024)
            atomicAdd(&hist[(cbuf[l] >> 10) & 0x7FFu], 1u);
    } else {
        for (int i = tid; i < TOKENS; i += 1024) {
            unsigned v = vals[i];
            if ((v >> 21) == pre11) atomicAdd(&hist[(v >> 10) & 0x7FFu], 1u);
        }
    }
    __syncthreads();
    block_select2048(hist, wtmp, krem, tid, &s_sel, &s_k);
    const unsigned pre22 = (pre11 << 11) | (unsigned)s_sel;
    krem = s_k;
    __syncthreads();

    // ---- pass 3: among (v>>10)==pre22, bins = v & 0x3FF ----
    hist[tid] = 0; hist[tid + 1024] = 0;
    __syncthreads();
    if (usec) {
        for (int l = tid; l < ncb; l += 1024) {
            unsigned v = cbuf[l];
            if ((v >> 10) == pre22) atomicAdd(&hist[v & 0x3FFu], 1u);
        }
    } else {
        for (int i = tid; i < TOKENS; i += 1024) {
            unsigned v = vals[i];
            if ((v >> 10) == pre22) atomicAdd(&hist[v & 0x3FFu], 1u);
        }
    }
    __syncthreads();
    block_select2048(hist, wtmp, krem, tid, &s_sel, &s_k);
    const unsigned th = (pre22 << 10) | (unsigned)s_sel;
    const int r = s_k;
    __syncthreads();

    // ---- fused collect: greater -> cand, equal -> eqbuf ----
    if (tid == 0) { s_cnt = 0; s_eqc = 0; }
    __syncthreads();
    for (int i = tid; i < TOKENS; i += 1024) {
        unsigned v = vals[i];
        if (v > th) {
            unsigned p = atomicAdd(&s_cnt, 1u);
            cand[p] = ((unsigned long long)v << 32) | (unsigned)(~(unsigned)i);
        } else if (v == th) {
            unsigned p = atomicAdd(&s_eqc, 1u);
            if (p < 2048u) eqbuf[p] = i;
        }
    }
    __syncthreads();
    const int cnt_eq = (int)s_eqc;
    const int eqbase = CAP - r;

    if (cnt_eq == r) {
        for (int l = tid; l < r; l += 1024)
            cand[eqbase + l] =
                ((unsigned long long)th << 32) | (unsigned)(~(unsigned)eqbuf[l]);
    } else if (cnt_eq <= 2048) {
        for (int l = tid; l < cnt_eq; l += 1024) {
            int idx = eqbuf[l];
            int rank = 0;
            for (int m = 0; m < cnt_eq; m++) rank += (eqbuf[m] < idx) ? 1 : 0;
            if (rank < r)
                cand[eqbase + rank] =
                    ((unsigned long long)th << 32) | (unsigned)(~(unsigned)idx);
        }
    } else {
        for (int i = tid; i < TOKENS; i += 1024) {
            if (vals[i] == th) {
                int rank = 0;
                for (int j = 0; j < i; j++) rank += (vals[j] == th) ? 1 : 0;
                if (rank < r)
                    cand[eqbase + rank] =
                        ((unsigned long long)th << 32) | (unsigned)(~(unsigned)i);
            }
        }
    }
    __syncthreads();

    // ---- hybrid bitonic sort: 1024 keys, DESC (val desc, idx asc) ----
    unsigned long long key = cand[tid];
#pragma unroll 1
    for (unsigned kk = 2; kk <= 1024; kk <<= 1) {
        unsigned j = kk >> 1;
        for (; j >= 32; j >>= 1) {
            cand[tid] = key;
            __syncthreads();
            unsigned long long p = cand[tid ^ j];
            bool up = ((tid & kk) == 0);
            bool lowr = ((tid & j) == 0);
            bool takeMax = (up == lowr);
            key = takeMax ? (key > p ? key : p) : (key > p ? p : key);
            __syncthreads();
        }
        for (; j >= 1; j >>= 1) {
            unsigned long long p = __shfl_xor_sync(0xffffffffu, key, j);
            bool up = ((tid & kk) == 0);
            bool lowr = ((tid & j) == 0);
            bool takeMax = (up == lowr);
            key = takeMax ? (key > p ? key : p) : (key > p ? p : key);
        }
    }

    unsigned m   = (unsigned)(key >> 32);
    unsigned idx = ~(unsigned)(key & 0xffffffffu);
    out_val[(size_t)e * CAP + tid] = mono_inv(m);
    out_idx[(size_t)e * CAP + tid] = (float)idx;
}

// ---------------- probs = fl( expf(l - M) / S ), vectorized x4 ------------
__global__ __launch_bounds__(256) void probs_kernel(
    const float* __restrict__ logits, float* __restrict__ probs)
{
    __shared__ float sM[64], sS[64];
    if (threadIdx.x < 64) {
        sM[threadIdx.x] = g_gmax[threadIdx.x];
        sS[threadIdx.x] = g_sum[threadIdx.x];
    }
    __syncthreads();
    int i4 = (blockIdx.x * 256 + threadIdx.x) * 4;
    float4 l = *(const float4*)(logits + i4);
    int e0 = i4 & 63;
    float4 p;
    p.x = __fdiv_rn(expf(__fsub_rn(l.x, sM[e0 + 0])), sS[e0 + 0]);
    p.y = __fdiv_rn(expf(__fsub_rn(l.y, sM[e0 + 1])), sS[e0 + 1]);
    p.z = __fdiv_rn(expf(__fsub_rn(l.z, sM[e0 + 2])), sS[e0 + 2]);
    p.w = __fdiv_rn(expf(__fsub_rn(l.w, sM[e0 + 3])), sS[e0 + 3]);
    *(float4*)(probs + i4) = p;
}

// ---------------- launch ----------------
extern "C" void kernel_launch(void* const* d_in, const int* in_sizes, int n_in,
                              void* d_out, int out_size)
{
    const float* x = (const float*)d_in[0];
    const float* W = (const float*)d_in[1];
    const float* b = (const float*)d_in[2];
    (void)in_sizes; (void)n_in; (void)out_size;

    float* out    = (float*)d_out;
    float* logits = out;                                  // 32768*64
    float* probs  = out + (size_t)TOKENS * NEXP;          // 32768*64
    float* ep     = out + 2 * (size_t)TOKENS * NEXP;      // 64*1024
    float* ei     = ep  + (size_t)NEXP * CAP;             // 64*1024

    cudaFuncSetAttribute(gemm_split2_kernel,
                         cudaFuncAttributeMaxDynamicSharedMemorySize, GEMM_SMEM);
    cudaFuncSetAttribute(topk_kernel,
                         cudaFuncAttributeMaxDynamicSharedMemorySize, TOPK_SMEM);

    gemm_split2_kernel<<<GEMM_BLOCKS, 256, GEMM_SMEM>>>(x, W, b, logits);
    topk_kernel<<<NEXP, 1024, TOPK_SMEM>>>(ep, ei);
    probs_kernel<<<(TOKENS * NEXP) / 1024, 256>>>(logits, probs);
}